// round 1
// baseline (speedup 1.0000x reference)
#include <cuda_runtime.h>
#include <cstdint>

// Node accumulator scratch (4 MB — fits comfortably in L2).
#define N_NODES 1000000
__device__ float g_rowsum[N_NODES];

// Detect whether edge_index is truly int64 or was demoted to int32 by JAX.
// int64 values are in [0, 1e6) -> high 32 bits of every 8-byte word are 0.
// int32 data read as 8-byte words has a random index in the high half
// (zero only with prob 1e-6 per word; we OR 4 words).
__device__ __forceinline__ bool detect_i64(const void* idx) {
    const unsigned long long* p = (const unsigned long long*)idx;
    unsigned long long h = p[0] | p[1] | p[2] | p[3];
    return (h >> 32) == 0ULL;
}

__device__ __forceinline__ float et_of(float x) {
    float lr = x > 0.0f ? x : 0.01f * x;
    return __expf(lr);
}

__global__ void zero_kernel() {
    int i = blockIdx.x * blockDim.x + threadIdx.x;
    if (i < N_NODES) g_rowsum[i] = 0.0f;
}

__global__ void accum_kernel(const void* __restrict__ idx,
                             const float* __restrict__ attr, int E) {
    int t = blockIdx.x * blockDim.x + threadIdx.x;
    int i0 = t * 4;
    if (i0 >= E) return;
    bool i64 = detect_i64(idx);

    if (i0 + 3 < E) {
        float4 a = *(const float4*)(attr + i0);
        int r0, r1, r2, r3;
        if (i64) {
            const longlong2* q = (const longlong2*)idx;
            longlong2 v0 = q[i0 >> 1];
            longlong2 v1 = q[(i0 >> 1) + 1];
            r0 = (int)v0.x; r1 = (int)v0.y; r2 = (int)v1.x; r3 = (int)v1.y;
        } else {
            int4 v = *(const int4*)((const int*)idx + i0);
            r0 = v.x; r1 = v.y; r2 = v.z; r3 = v.w;
        }
        atomicAdd(&g_rowsum[r0], et_of(a.x));
        atomicAdd(&g_rowsum[r1], et_of(a.y));
        atomicAdd(&g_rowsum[r2], et_of(a.z));
        atomicAdd(&g_rowsum[r3], et_of(a.w));
    } else {
        for (int i = i0; i < E; i++) {
            int r = i64 ? (int)((const long long*)idx)[i]
                        : ((const int*)idx)[i];
            atomicAdd(&g_rowsum[r], et_of(attr[i]));
        }
    }
}

__global__ void recip_kernel() {
    int i = blockIdx.x * blockDim.x + threadIdx.x;
    if (i < N_NODES) g_rowsum[i] = 1.0f / g_rowsum[i];
}

__global__ void norm_kernel(const void* __restrict__ idx,
                            const float* __restrict__ attr,
                            float* __restrict__ out, int E) {
    int t = blockIdx.x * blockDim.x + threadIdx.x;
    int i0 = t * 4;
    if (i0 >= E) return;
    bool i64 = detect_i64(idx);

    if (i0 + 3 < E) {
        float4 a = *(const float4*)(attr + i0);
        int r0, r1, r2, r3;
        if (i64) {
            const longlong2* q = (const longlong2*)idx;
            longlong2 v0 = q[i0 >> 1];
            longlong2 v1 = q[(i0 >> 1) + 1];
            r0 = (int)v0.x; r1 = (int)v0.y; r2 = (int)v1.x; r3 = (int)v1.y;
        } else {
            int4 v = *(const int4*)((const int*)idx + i0);
            r0 = v.x; r1 = v.y; r2 = v.z; r3 = v.w;
        }
        float4 o;
        o.x = et_of(a.x) * g_rowsum[r0];
        o.y = et_of(a.y) * g_rowsum[r1];
        o.z = et_of(a.z) * g_rowsum[r2];
        o.w = et_of(a.w) * g_rowsum[r3];
        *(float4*)(out + i0) = o;
    } else {
        for (int i = i0; i < E; i++) {
            int r = i64 ? (int)((const long long*)idx)[i]
                        : ((const int*)idx)[i];
            out[i] = et_of(attr[i]) * g_rowsum[r];
        }
    }
}

extern "C" void kernel_launch(void* const* d_in, const int* in_sizes, int n_in,
                              void* d_out, int out_size) {
    const void*  edge_index = d_in[0];               // [2, E] (row = first E)
    const float* edge_attr  = (const float*)d_in[1]; // [E]
    float*       out        = (float*)d_out;
    int E = in_sizes[1];

    const int T = 256;
    int zblocks = (N_NODES + T - 1) / T;
    int eblocks = ((E + 3) / 4 + T - 1) / T;

    zero_kernel<<<zblocks, T>>>();
    accum_kernel<<<eblocks, T>>>(edge_index, edge_attr, E);
    recip_kernel<<<zblocks, T>>>();
    norm_kernel<<<eblocks, T>>>(edge_index, edge_attr, out, E);
}